// round 3
// baseline (speedup 1.0000x reference)
#include <cuda_runtime.h>
#include <cstdint>

// ---------------------------------------------------------------------------
// GCN layer: out = relu( D_in^-1/2 · A · D_out^-1/2 · (X @ W) + b )
// N=100000, E=1600000, IN=256, OUT=32  (fp32)
// NOTE: src/dst are int32 (JAX default x64-disabled downcasts int64->int32).
//
// Pipeline (no float atomics anywhere):
//   k_zero      : zero degree + cursor arrays
//   k_deg       : out_deg[src]++ , in_deg[dst]++       (u32 atomics)
//   k_scanA/B/C : exclusive prefix sum of in_deg -> g_off (CSR row offsets)
//   k_fill      : CSR fill: g_esrc[g_off[dst] + cursor[dst]++] = src
//   k_gemm      : g_h[n] = (feat[n] @ W) * out_deg[n]^-1/2
//   k_agg       : warp-per-dst gather-sum, fused *in_deg^-1/2, +bias, relu
// ---------------------------------------------------------------------------

#define NMAX 100000
#define EMAX 1600000
#define IN_F 256
#define OUT_F 32
#define SCAN_BLK 512
#define SCAN_NBLK ((NMAX + SCAN_BLK - 1) / SCAN_BLK)   // 196

__device__ unsigned g_outdeg[NMAX];
__device__ unsigned g_indeg[NMAX];
__device__ unsigned g_cursor[NMAX];
__device__ unsigned g_off[NMAX];
__device__ unsigned g_bsum[SCAN_NBLK];
__device__ int      g_esrc[EMAX];
__device__ __align__(16) float g_h[(size_t)NMAX * OUT_F];

// ---------------------------------------------------------------------------
__global__ void k_zero(int n_nodes) {
    int i = blockIdx.x * blockDim.x + threadIdx.x;
    if (i < n_nodes) {
        g_outdeg[i] = 0u;
        g_indeg[i]  = 0u;
        g_cursor[i] = 0u;
    }
}

// ---------------------------------------------------------------------------
__global__ void k_deg(const int* __restrict__ src,
                      const int* __restrict__ dst, int E) {
    int i = blockIdx.x * blockDim.x + threadIdx.x;
    if (i < E) {
        atomicAdd(&g_outdeg[src[i]], 1u);
        atomicAdd(&g_indeg[dst[i]], 1u);
    }
}

// --------------------------- 3-kernel exclusive scan -----------------------
__global__ void k_scanA(int n_nodes) {
    __shared__ unsigned s[SCAN_BLK];
    int t = threadIdx.x;
    int i = blockIdx.x * SCAN_BLK + t;
    unsigned v = (i < n_nodes) ? g_indeg[i] : 0u;
    s[t] = v;
    __syncthreads();
    for (int off = 1; off < SCAN_BLK; off <<= 1) {
        unsigned x = (t >= off) ? s[t - off] : 0u;
        __syncthreads();
        s[t] += x;
        __syncthreads();
    }
    if (i < n_nodes) g_off[i] = s[t] - v;          // exclusive
    if (t == SCAN_BLK - 1) g_bsum[blockIdx.x] = s[t];
}

__global__ void k_scanB() {
    __shared__ unsigned s[256];
    int t = threadIdx.x;
    unsigned v = (t < SCAN_NBLK) ? g_bsum[t] : 0u;
    s[t] = v;
    __syncthreads();
    for (int off = 1; off < 256; off <<= 1) {
        unsigned x = (t >= off) ? s[t - off] : 0u;
        __syncthreads();
        s[t] += x;
        __syncthreads();
    }
    if (t < SCAN_NBLK) g_bsum[t] = s[t] - v;       // exclusive
}

__global__ void k_scanC(int n_nodes) {
    int i = blockIdx.x * blockDim.x + threadIdx.x;
    if (i < n_nodes) g_off[i] += g_bsum[i / SCAN_BLK];
}

// ---------------------------------------------------------------------------
__global__ void k_fill(const int* __restrict__ src,
                       const int* __restrict__ dst, int E) {
    int i = blockIdx.x * blockDim.x + threadIdx.x;
    if (i < E) {
        int d = dst[i];
        unsigned pos = g_off[d] + atomicAdd(&g_cursor[d], 1u);
        g_esrc[pos] = src[i];
    }
}

// ---------------------------------------------------------------------------
// GEMM: 16-row tile, 256 threads (8 warps). Warp owns 2 rows; lane = out col.
// smem: W 32KB + feat tile 16KB = 48KB static.
__global__ void k_gemm(const float* __restrict__ feat,
                       const float* __restrict__ W, int n_nodes) {
    __shared__ float sW[IN_F * OUT_F];
    __shared__ float sF[16 * IN_F];

    const int tid  = threadIdx.x;
    const int lane = tid & 31;
    const int warp = tid >> 5;
    const int row0 = blockIdx.x * 16;

    for (int i = tid; i < (IN_F * OUT_F) / 4; i += 256)
        ((float4*)sW)[i] = ((const float4*)W)[i];

    for (int i = tid; i < 16 * (IN_F / 4); i += 256) {
        int r = i >> 6, c = i & 63;
        int row = row0 + r;
        ((float4*)sF)[i] = (row < n_nodes)
            ? ((const float4*)feat)[(size_t)row * 64 + c]
            : make_float4(0.f, 0.f, 0.f, 0.f);
    }
    __syncthreads();

    float acc0 = 0.f, acc1 = 0.f;
    const int rbase = warp * 2;

    for (int kc = 0; kc < 4; ++kc) {
        float wreg[64];
        #pragma unroll
        for (int kk = 0; kk < 64; ++kk)
            wreg[kk] = sW[(kc * 64 + kk) * OUT_F + lane];

        const float* f0 = &sF[(rbase + 0) * IN_F + kc * 64];
        const float* f1 = &sF[(rbase + 1) * IN_F + kc * 64];
        #pragma unroll
        for (int kk = 0; kk < 64; ++kk) {
            acc0 = fmaf(f0[kk], wreg[kk], acc0);
            acc1 = fmaf(f1[kk], wreg[kk], acc1);
        }
    }

    #pragma unroll
    for (int r = 0; r < 2; ++r) {
        int row = row0 + rbase + r;
        if (row < n_nodes) {
            unsigned d = g_outdeg[row];
            float s = rsqrtf((float)(d ? d : 1u));
            g_h[(size_t)row * OUT_F + lane] = ((r == 0) ? acc0 : acc1) * s;
        }
    }
}

// ---------------------------------------------------------------------------
// Aggregation: warp per destination node. Lane j owns output column j.
// Lanes cooperatively load up to 32 CSR src ids, broadcast via shfl,
// each lane accumulates its column from L2-resident g_h.
__global__ void k_agg(float* __restrict__ out,
                      const float* __restrict__ bias, int n_nodes) {
    int warp = (blockIdx.x * blockDim.x + threadIdx.x) >> 5;
    int lane = threadIdx.x & 31;
    if (warp >= n_nodes) return;

    unsigned off = g_off[warp];
    unsigned deg = g_indeg[warp];

    float acc = 0.f;
    for (unsigned c = 0; c < deg; c += 32) {
        unsigned rem = deg - c;
        unsigned cnt = rem < 32u ? rem : 32u;
        int e = (lane < cnt) ? g_esrc[off + c + lane] : 0;
        for (unsigned j = 0; j < cnt; ++j) {
            int s = __shfl_sync(0xFFFFFFFFu, e, j);
            acc += g_h[(size_t)s * OUT_F + lane];
        }
    }

    float sc = rsqrtf((float)(deg ? deg : 1u));
    float v = fmaf(acc, sc, bias[lane]);
    out[(size_t)warp * OUT_F + lane] = fmaxf(v, 0.f);
}

// ---------------------------------------------------------------------------
extern "C" void kernel_launch(void* const* d_in, const int* in_sizes, int n_in,
                              void* d_out, int out_size) {
    const float* feat = (const float*)d_in[0];
    const int*   src  = (const int*)d_in[1];
    const int*   dst  = (const int*)d_in[2];
    const float* W    = (const float*)d_in[3];
    const float* bias = (const float*)d_in[4];
    float* out = (float*)d_out;

    const int N = in_sizes[0] / IN_F;
    const int E = in_sizes[1];

    k_zero<<<(N + 255) / 256, 256>>>(N);
    k_deg<<<(E + 255) / 256, 256>>>(src, dst, E);
    k_scanA<<<(N + SCAN_BLK - 1) / SCAN_BLK, SCAN_BLK>>>(N);
    k_scanB<<<1, 256>>>();
    k_scanC<<<(N + 255) / 256, 256>>>(N);
    k_fill<<<(E + 255) / 256, 256>>>(src, dst, E);
    k_gemm<<<(N + 15) / 16, 256>>>(feat, W, N);
    k_agg<<<(N * 32 + 255) / 256, 256>>>(out, bias, N);
}

// round 4
// speedup vs baseline: 1.0660x; 1.0660x over previous
#include <cuda_runtime.h>
#include <cstdint>

// ---------------------------------------------------------------------------
// GCN layer: out = relu( D_in^-1/2 · A · D_out^-1/2 · (X @ W) + b )
// N=100000, E=1600000, IN=256, OUT=32  (fp32, src/dst int32)
//
// Pipeline:
//   k_zero   : zero degree arrays
//   k_deg    : out_deg[src]++ , in_deg[dst]++           (u32 atomics)
//   k_scanA/B: two-level exclusive scan of in_deg -> g_off (+g_bsum)
//   k_fill   : CSR fill, cursor fused into g_off via atomicAdd
//   k_gemm   : g_h[n] = (feat[n] @ W) * out_deg[n]^-1/2  (packed f32x2 FMA)
//   k_agg    : warp-per-dst gather-sum, fused *in_deg^-1/2, +bias, relu
// ---------------------------------------------------------------------------

#define NMAX 100000
#define EMAX 1600000
#define IN_F 256
#define OUT_F 32
#define SCAN_BLK 512
#define SCAN_SHIFT 9
#define SCAN_NBLK ((NMAX + SCAN_BLK - 1) / SCAN_BLK)   // 196

#define TILE_R 64                       // gemm rows per block
#define FP_STRIDE 33                    // float2 pairs per k-row (32 + 1 pad)
#define GEMM_SMEM (IN_F * OUT_F * 4 + IN_F * FP_STRIDE * 8)   // 32KB + 66KB

__device__ unsigned g_outdeg[NMAX];
__device__ unsigned g_indeg[NMAX];
__device__ unsigned g_off[NMAX];
__device__ unsigned g_bsum[SCAN_NBLK];
__device__ int      g_esrc[EMAX];
__device__ __align__(16) float g_h[(size_t)NMAX * OUT_F];

// packed f32x2 helpers --------------------------------------------------------
#define FMA_F32X2(acc, a, b) \
    asm("fma.rn.f32x2 %0, %1, %2, %0;" : "+l"(acc) : "l"(a), "l"(b))
#define PACK_DUP_F32X2(out, w) \
    asm("mov.b64 %0, {%1, %1};" : "=l"(out) : "f"(w))
#define UNPACK_F32X2(lo, hi, in) \
    asm("mov.b64 {%0, %1}, %2;" : "=f"(lo), "=f"(hi) : "l"(in))

// ---------------------------------------------------------------------------
__global__ void k_zero(int n_nodes) {
    int i = blockIdx.x * blockDim.x + threadIdx.x;
    if (i < n_nodes) {
        g_outdeg[i] = 0u;
        g_indeg[i]  = 0u;
    }
}

// ---------------------------------------------------------------------------
__global__ void k_deg(const int* __restrict__ src,
                      const int* __restrict__ dst, int E) {
    int i = blockIdx.x * blockDim.x + threadIdx.x;
    if (i < E) {
        atomicAdd(&g_outdeg[src[i]], 1u);
        atomicAdd(&g_indeg[dst[i]], 1u);
    }
}

// --------------------------- two-level exclusive scan -----------------------
__global__ void k_scanA(int n_nodes) {
    __shared__ unsigned s[SCAN_BLK];
    int t = threadIdx.x;
    int i = blockIdx.x * SCAN_BLK + t;
    unsigned v = (i < n_nodes) ? g_indeg[i] : 0u;
    s[t] = v;
    __syncthreads();
    for (int off = 1; off < SCAN_BLK; off <<= 1) {
        unsigned x = (t >= off) ? s[t - off] : 0u;
        __syncthreads();
        s[t] += x;
        __syncthreads();
    }
    if (i < n_nodes) g_off[i] = s[t] - v;          // block-local exclusive
    if (t == SCAN_BLK - 1) g_bsum[blockIdx.x] = s[t];
}

__global__ void k_scanB() {
    __shared__ unsigned s[256];
    int t = threadIdx.x;
    unsigned v = (t < SCAN_NBLK) ? g_bsum[t] : 0u;
    s[t] = v;
    __syncthreads();
    for (int off = 1; off < 256; off <<= 1) {
        unsigned x = (t >= off) ? s[t - off] : 0u;
        __syncthreads();
        s[t] += x;
        __syncthreads();
    }
    if (t < SCAN_NBLK) g_bsum[t] = s[t] - v;       // exclusive block sums
}

// ---------------------------------------------------------------------------
// CSR fill: cursor fused into g_off (atomic bump). After this kernel,
// g_off[d] == local_excl_prefix[d] + in_deg[d]  (i.e. local END offset).
__global__ void k_fill(const int* __restrict__ src,
                       const int* __restrict__ dst, int E) {
    int i = blockIdx.x * blockDim.x + threadIdx.x;
    if (i < E) {
        int d = dst[i];
        unsigned pos = atomicAdd(&g_off[d], 1u) + g_bsum[d >> SCAN_SHIFT];
        g_esrc[pos] = src[i];
    }
}

// ---------------------------------------------------------------------------
// GEMM with packed f32x2 FMA. Block = 256 threads (8 warps), 64-row tile.
// smem layout (dynamic, 98KB):
//   sW  [256][32]  floats                           (32KB)
//   sFP [256 k][33 pairs] float2 (row-pair interleave, 1-pair pad)  (66KB)
// Warp owns 4 row-pairs (8 rows); lane = output column. Inner loop:
//   acc2(rowpair) += LDS.b64(fpair, broadcast) * w2(prepacked reg)  -> FFMA2
__global__ void __launch_bounds__(256, 2)
k_gemm(const float* __restrict__ feat, const float* __restrict__ W,
       int n_nodes) {
    extern __shared__ float smem[];
    float* sW = smem;                                    // 8192 floats
    float* sFPf = smem + IN_F * OUT_F;                   // transposed tile
    unsigned long long* sFPu = (unsigned long long*)sFPf;

    const int tid  = threadIdx.x;
    const int lane = tid & 31;
    const int warp = tid >> 5;
    const int row0 = blockIdx.x * TILE_R;

    // load W [256][32] coalesced
    for (int i = tid; i < (IN_F * OUT_F) / 4; i += 256)
        ((float4*)sW)[i] = ((const float4*)W)[i];

    // transpose-load feat tile: scalar loads, lanes span k (coalesced LDG.32),
    // store to sFPf[k*66 + r_local] (2-way bank conflict only).
    for (int it = 0; it < TILE_R; ++it) {
        int idx = tid + 256 * it;          // idx = r_local*256 + k
        int rl = idx >> 8;
        int k  = idx & 255;
        int row = row0 + rl;
        float v = (row < n_nodes) ? feat[(size_t)row * IN_F + k] : 0.f;
        sFPf[k * (2 * FP_STRIDE) + rl] = v;
    }
    __syncthreads();

    unsigned long long acc[4];
    acc[0] = acc[1] = acc[2] = acc[3] = 0ull;   // (0.f, 0.f) packed
    const int pbase = warp * 4;                 // 4 row-pairs per warp

    for (int kc = 0; kc < IN_F / 32; ++kc) {    // 8 chunks of 32 k
        unsigned long long w2[32];
        #pragma unroll
        for (int kk = 0; kk < 32; ++kk) {
            float w = sW[(kc * 32 + kk) * OUT_F + lane];
            PACK_DUP_F32X2(w2[kk], w);
        }
        #pragma unroll
        for (int rp = 0; rp < 4; ++rp) {
            const unsigned long long* f = &sFPu[(size_t)(kc * 32) * FP_STRIDE
                                                + pbase + rp];
            #pragma unroll
            for (int kk = 0; kk < 32; ++kk) {
                unsigned long long f2 = f[kk * FP_STRIDE];   // LDS.b64 bcast
                FMA_F32X2(acc[rp], f2, w2[kk]);
            }
        }
    }

    // epilogue: unpack, scale by out_deg^-1/2, store
    #pragma unroll
    for (int rp = 0; rp < 4; ++rp) {
        float a0, a1;
        UNPACK_F32X2(a0, a1, acc[rp]);
        int r0 = row0 + (pbase + rp) * 2;
        if (r0 < n_nodes) {
            unsigned d = g_outdeg[r0];
            g_h[(size_t)r0 * OUT_F + lane] = a0 * rsqrtf((float)(d ? d : 1u));
        }
        if (r0 + 1 < n_nodes) {
            unsigned d = g_outdeg[r0 + 1];
            g_h[(size_t)(r0 + 1) * OUT_F + lane] =
                a1 * rsqrtf((float)(d ? d : 1u));
        }
    }
}

// ---------------------------------------------------------------------------
// Aggregation: warp per destination node, lane = output column.
// g_off[d] now holds local END offset; start = end + bsum - deg.
__global__ void k_agg(float* __restrict__ out,
                      const float* __restrict__ bias, int n_nodes) {
    int warp = (blockIdx.x * blockDim.x + threadIdx.x) >> 5;
    int lane = threadIdx.x & 31;
    if (warp >= n_nodes) return;

    unsigned deg = g_indeg[warp];
    unsigned off = g_off[warp] + g_bsum[warp >> SCAN_SHIFT] - deg;

    float acc0 = 0.f, acc1 = 0.f;
    for (unsigned c = 0; c < deg; c += 32) {
        unsigned rem = deg - c;
        unsigned cnt = rem < 32u ? rem : 32u;
        int e = (lane < cnt) ? g_esrc[off + c + lane] : 0;
        unsigned j = 0;
        for (; j + 2 <= cnt; j += 2) {
            int s0 = __shfl_sync(0xFFFFFFFFu, e, j);
            int s1 = __shfl_sync(0xFFFFFFFFu, e, j + 1);
            acc0 += g_h[(size_t)s0 * OUT_F + lane];
            acc1 += g_h[(size_t)s1 * OUT_F + lane];
        }
        if (j < cnt) {
            int s0 = __shfl_sync(0xFFFFFFFFu, e, j);
            acc0 += g_h[(size_t)s0 * OUT_F + lane];
        }
    }

    float sc = rsqrtf((float)(deg ? deg : 1u));
    float v = fmaf(acc0 + acc1, sc, bias[lane]);
    out[(size_t)warp * OUT_F + lane] = fmaxf(v, 0.f);
}

// ---------------------------------------------------------------------------
extern "C" void kernel_launch(void* const* d_in, const int* in_sizes, int n_in,
                              void* d_out, int out_size) {
    const float* feat = (const float*)d_in[0];
    const int*   src  = (const int*)d_in[1];
    const int*   dst  = (const int*)d_in[2];
    const float* W    = (const float*)d_in[3];
    const float* bias = (const float*)d_in[4];
    float* out = (float*)d_out;

    const int N = in_sizes[0] / IN_F;
    const int E = in_sizes[1];

    cudaFuncSetAttribute(k_gemm, cudaFuncAttributeMaxDynamicSharedMemorySize,
                         GEMM_SMEM);

    k_zero<<<(N + 255) / 256, 256>>>(N);
    k_deg<<<(E + 255) / 256, 256>>>(src, dst, E);
    k_scanA<<<(N + SCAN_BLK - 1) / SCAN_BLK, SCAN_BLK>>>(N);
    k_scanB<<<1, 256>>>();
    k_fill<<<(E + 255) / 256, 256>>>(src, dst, E);
    k_gemm<<<(N + TILE_R - 1) / TILE_R, 256, GEMM_SMEM>>>(feat, W, N);
    k_agg<<<(N * 32 + 255) / 256, 256>>>(out, bias, N);
}

// round 5
// speedup vs baseline: 1.1444x; 1.0735x over previous
#include <cuda_runtime.h>
#include <cstdint>

// ---------------------------------------------------------------------------
// GCN layer: out = relu( D_in^-1/2 · A · D_out^-1/2 · (X @ W) + b )
// N=100000, E=1600000, IN=256, OUT=32  (fp32, src/dst int32)
//
// Graph (forked):
//   zero -> deg -> +-> gemm (side stream)      -+-> agg
//                  +-> scan -> fill (main)     -+
// ---------------------------------------------------------------------------

#define NMAX 100000
#define EMAX 1600000
#define IN_F 256
#define OUT_F 32
#define SCAN_BLK 512
#define SCAN_SHIFT 9
#define SCAN_NBLK ((NMAX + SCAN_BLK - 1) / SCAN_BLK)   // 196

#define TILE_R 64
#define FP_STRIDE 33
#define GEMM_SMEM (IN_F * OUT_F * 4 + IN_F * FP_STRIDE * 8)   // 98KB

__device__ unsigned g_outdeg[NMAX];
__device__ unsigned g_indeg[NMAX];
__device__ unsigned g_off[NMAX];
__device__ unsigned g_bsum[SCAN_NBLK];
__device__ unsigned g_scan_ctr;
__device__ int      g_esrc[EMAX];
__device__ __align__(16) float g_h[(size_t)NMAX * OUT_F];

// packed f32x2 helpers -------------------------------------------------------
#define FMA_F32X2(acc, a, b) \
    asm("fma.rn.f32x2 %0, %1, %2, %0;" : "+l"(acc) : "l"(a), "l"(b))
#define PACK_DUP_F32X2(out, w) \
    asm("mov.b64 %0, {%1, %1};" : "=l"(out) : "f"(w))
#define UNPACK_F32X2(lo, hi, in) \
    asm("mov.b64 {%0, %1}, %2;" : "=f"(lo), "=f"(hi) : "l"(in))

// ---------------------------------------------------------------------------
__global__ void k_zero(int n_nodes) {
    int i = blockIdx.x * blockDim.x + threadIdx.x;
    if (i < n_nodes) {
        g_outdeg[i] = 0u;
        g_indeg[i]  = 0u;
    }
    if (i == 0) g_scan_ctr = 0u;
}

// ---------------------------------------------------------------------------
__global__ void k_deg(const int* __restrict__ src,
                      const int* __restrict__ dst, int E) {
    int i = blockIdx.x * blockDim.x + threadIdx.x;
    if (i < E) {
        atomicAdd(&g_outdeg[src[i]], 1u);
        atomicAdd(&g_indeg[dst[i]], 1u);
    }
}

// ---------------------------------------------------------------------------
// Single-pass two-level scan: each block scans its 512 chunk -> g_off (local
// exclusive) + g_bsum[b]; the LAST block to finish exclusive-scans g_bsum.
__global__ void k_scan(int n_nodes) {
    __shared__ unsigned s[SCAN_BLK];
    __shared__ bool is_last;
    int t = threadIdx.x;
    int i = blockIdx.x * SCAN_BLK + t;
    unsigned v = (i < n_nodes) ? g_indeg[i] : 0u;
    s[t] = v;
    __syncthreads();
    for (int off = 1; off < SCAN_BLK; off <<= 1) {
        unsigned x = (t >= off) ? s[t - off] : 0u;
        __syncthreads();
        s[t] += x;
        __syncthreads();
    }
    if (i < n_nodes) g_off[i] = s[t] - v;          // block-local exclusive
    if (t == SCAN_BLK - 1) g_bsum[blockIdx.x] = s[t];

    // last-block aggregation of g_bsum
    __threadfence();
    if (t == 0) {
        unsigned done = atomicAdd(&g_scan_ctr, 1u);
        is_last = (done == (unsigned)(gridDim.x - 1));
    }
    __syncthreads();
    if (is_last) {
        __threadfence();
        unsigned bv = (t < SCAN_NBLK) ? g_bsum[t] : 0u;
        s[t] = bv;
        __syncthreads();
        for (int off = 1; off < 256; off <<= 1) {
            unsigned x = (t >= off && t < 256) ? s[t - off] : 0u;
            __syncthreads();
            if (t < 256) s[t] += x;
            __syncthreads();
        }
        if (t < SCAN_NBLK) g_bsum[t] = s[t] - bv;  // exclusive block sums
    }
}

// ---------------------------------------------------------------------------
// CSR fill: cursor fused into g_off (atomic bump). Afterwards
// g_off[d] == local exclusive prefix + in_deg[d]  (local END offset).
__global__ void k_fill(const int* __restrict__ src,
                       const int* __restrict__ dst, int E) {
    int i = blockIdx.x * blockDim.x + threadIdx.x;
    if (i < E) {
        int d = dst[i];
        unsigned pos = atomicAdd(&g_off[d], 1u) + g_bsum[d >> SCAN_SHIFT];
        g_esrc[pos] = src[i];
    }
}

// ---------------------------------------------------------------------------
// GEMM with packed f32x2 FMA. 256 threads, 64-row tile, 98KB dynamic smem.
__global__ void __launch_bounds__(256, 2)
k_gemm(const float* __restrict__ feat, const float* __restrict__ W,
       int n_nodes) {
    extern __shared__ float smem[];
    float* sW = smem;                                    // [256][32]
    float* sFPf = smem + IN_F * OUT_F;                   // [256 k][66 floats]
    unsigned long long* sFPu = (unsigned long long*)sFPf;

    const int tid  = threadIdx.x;
    const int lane = tid & 31;
    const int warp = tid >> 5;
    const int row0 = blockIdx.x * TILE_R;

    for (int i = tid; i < (IN_F * OUT_F) / 4; i += 256)
        ((float4*)sW)[i] = ((const float4*)W)[i];

    // transpose-load feat tile (coalesced LDG.32, 2-way-conflict STS)
    for (int it = 0; it < TILE_R; ++it) {
        int idx = tid + 256 * it;          // idx = r_local*256 + k
        int rl = idx >> 8;
        int k  = idx & 255;
        int row = row0 + rl;
        float v = (row < n_nodes) ? feat[(size_t)row * IN_F + k] : 0.f;
        sFPf[k * (2 * FP_STRIDE) + rl] = v;
    }
    __syncthreads();

    unsigned long long acc[4];
    acc[0] = acc[1] = acc[2] = acc[3] = 0ull;
    const int pbase = warp * 4;                 // 4 row-pairs per warp

    for (int kc = 0; kc < IN_F / 32; ++kc) {
        unsigned long long w2[32];
        #pragma unroll
        for (int kk = 0; kk < 32; ++kk) {
            float w = sW[(kc * 32 + kk) * OUT_F + lane];
            PACK_DUP_F32X2(w2[kk], w);
        }
        #pragma unroll
        for (int rp = 0; rp < 4; ++rp) {
            const unsigned long long* f = &sFPu[(size_t)(kc * 32) * FP_STRIDE
                                                + pbase + rp];
            #pragma unroll
            for (int kk = 0; kk < 32; ++kk) {
                unsigned long long f2 = f[kk * FP_STRIDE];   // LDS.b64 bcast
                FMA_F32X2(acc[rp], f2, w2[kk]);
            }
        }
    }

    #pragma unroll
    for (int rp = 0; rp < 4; ++rp) {
        float a0, a1;
        UNPACK_F32X2(a0, a1, acc[rp]);
        int r0 = row0 + (pbase + rp) * 2;
        if (r0 < n_nodes) {
            unsigned d = g_outdeg[r0];
            g_h[(size_t)r0 * OUT_F + lane] = a0 * rsqrtf((float)(d ? d : 1u));
        }
        if (r0 + 1 < n_nodes) {
            unsigned d = g_outdeg[r0 + 1];
            g_h[(size_t)(r0 + 1) * OUT_F + lane] =
                a1 * rsqrtf((float)(d ? d : 1u));
        }
    }
}

// ---------------------------------------------------------------------------
// Aggregation: warp per destination node, lane = output column.
__global__ void k_agg(float* __restrict__ out,
                      const float* __restrict__ bias, int n_nodes) {
    int warp = (blockIdx.x * blockDim.x + threadIdx.x) >> 5;
    int lane = threadIdx.x & 31;
    if (warp >= n_nodes) return;

    unsigned deg = g_indeg[warp];
    unsigned off = g_off[warp] + g_bsum[warp >> SCAN_SHIFT] - deg;

    float acc0 = 0.f, acc1 = 0.f;
    for (unsigned c = 0; c < deg; c += 32) {
        unsigned rem = deg - c;
        unsigned cnt = rem < 32u ? rem : 32u;
        int e = (lane < cnt) ? g_esrc[off + c + lane] : 0;
        unsigned j = 0;
        for (; j + 2 <= cnt; j += 2) {
            int s0 = __shfl_sync(0xFFFFFFFFu, e, j);
            int s1 = __shfl_sync(0xFFFFFFFFu, e, j + 1);
            acc0 += g_h[(size_t)s0 * OUT_F + lane];
            acc1 += g_h[(size_t)s1 * OUT_F + lane];
        }
        if (j < cnt) {
            int s0 = __shfl_sync(0xFFFFFFFFu, e, j);
            acc0 += g_h[(size_t)s0 * OUT_F + lane];
        }
    }

    float sc = rsqrtf((float)(deg ? deg : 1u));
    float v = fmaf(acc0 + acc1, sc, bias[lane]);
    out[(size_t)warp * OUT_F + lane] = fmaxf(v, 0.f);
}

// ---------------------------------------------------------------------------
extern "C" void kernel_launch(void* const* d_in, const int* in_sizes, int n_in,
                              void* d_out, int out_size) {
    const float* feat = (const float*)d_in[0];
    const int*   src  = (const int*)d_in[1];
    const int*   dst  = (const int*)d_in[2];
    const float* W    = (const float*)d_in[3];
    const float* bias = (const float*)d_in[4];
    float* out = (float*)d_out;

    const int N = in_sizes[0] / IN_F;
    const int E = in_sizes[1];

    cudaFuncSetAttribute(k_gemm, cudaFuncAttributeMaxDynamicSharedMemorySize,
                         GEMM_SMEM);

    // side stream + fork/join events (host objects only; kernel_launch is
    // invoked only for the correctness run and the capture run, so the
    // undestroyed handles are a few host objects, not device memory)
    cudaStream_t side;
    cudaEvent_t ev_fork, ev_join;
    cudaStreamCreateWithFlags(&side, cudaStreamNonBlocking);
    cudaEventCreateWithFlags(&ev_fork, cudaEventDisableTiming);
    cudaEventCreateWithFlags(&ev_join, cudaEventDisableTiming);

    // main stream (legacy default): zero -> deg
    k_zero<<<(N + 255) / 256, 256>>>(N);
    k_deg<<<(E + 255) / 256, 256>>>(src, dst, E);

    // fork: gemm on side stream (depends only on deg)
    cudaEventRecord(ev_fork, 0);
    cudaStreamWaitEvent(side, ev_fork, 0);
    k_gemm<<<(N + TILE_R - 1) / TILE_R, 256, GEMM_SMEM, side>>>(feat, W, N);
    cudaEventRecord(ev_join, side);

    // main: scan -> fill (CSR build), concurrent with gemm
    k_scan<<<SCAN_NBLK, SCAN_BLK>>>(N);
    k_fill<<<(E + 255) / 256, 256>>>(src, dst, E);

    // join, then aggregate
    cudaStreamWaitEvent(0, ev_join, 0);
    k_agg<<<(N * 32 + 255) / 256, 256>>>(out, bias, N);
}